// round 2
// baseline (speedup 1.0000x reference)
#include <cuda_runtime.h>

#define N_NODES 50000
#define N_EDGES 800000
#define D 256
#define NL 3
#define BN_EPS 1e-5f

// ---------------- device scratch (no allocations allowed) ----------------
__device__ int   g_deg[N_NODES];
__device__ int   g_rowptr[N_NODES + 1];
__device__ int   g_cursor[N_NODES];
__device__ int   g_csr[N_EDGES];
__device__ float g_agg[(size_t)N_NODES * D];
__device__ float g_h[(size_t)N_NODES * D];
__device__ float g_xa[(size_t)N_NODES * D];
__device__ float g_xb[(size_t)N_NODES * D];
__device__ float g_sums[2 * D];   // [0:D) = sum, [D:2D) = sum of squares
__device__ float g_ss[2 * D];     // [0:D) = scale, [D:2D) = shift

// ---------------- CSR build ----------------
__global__ void k_zero_deg() {
    int i = blockIdx.x * blockDim.x + threadIdx.x;
    if (i < N_NODES) g_deg[i] = 0;
}

__global__ void k_count(const int* __restrict__ dst) {
    int e = blockIdx.x * blockDim.x + threadIdx.x;
    if (e < N_EDGES) {
        int d = dst[e];
        if (d >= 0 && d < N_NODES) atomicAdd(&g_deg[d], 1);
    }
}

// single-block exclusive scan of g_deg -> g_rowptr (and g_cursor copy)
__global__ void k_scan() {
    __shared__ int s[1024];
    __shared__ int carry_s;
    int tid = threadIdx.x;
    if (tid == 0) carry_s = 0;
    __syncthreads();
    for (int base = 0; base < N_NODES; base += 1024) {
        int i = base + tid;
        int v = (i < N_NODES) ? g_deg[i] : 0;
        s[tid] = v;
        __syncthreads();
        #pragma unroll
        for (int off = 1; off < 1024; off <<= 1) {
            int t = (tid >= off) ? s[tid - off] : 0;
            __syncthreads();
            s[tid] += t;
            __syncthreads();
        }
        int carry = carry_s;
        if (i < N_NODES) {
            int excl = carry + s[tid] - v;
            g_rowptr[i] = excl;
            g_cursor[i] = excl;
        }
        __syncthreads();
        if (tid == 1023) carry_s = carry + s[1023];
        __syncthreads();
    }
    if (tid == 0) g_rowptr[N_NODES] = carry_s;
}

__global__ void k_scatter(const int* __restrict__ src,
                          const int* __restrict__ dst) {
    int e = blockIdx.x * blockDim.x + threadIdx.x;
    if (e < N_EDGES) {
        int d = dst[e];
        int s = src[e];
        if (d >= 0 && d < N_NODES && s >= 0 && s < N_NODES) {
            int pos = atomicAdd(&g_cursor[d], 1);
            g_csr[pos] = s;
        }
    }
}

// ---------------- mean aggregation: one node per block ----------------
// sel: -1 -> external x, 0 -> g_xa, 1 -> g_xb
__global__ void k_agg(const float* __restrict__ xext, int sel) {
    const float* __restrict__ x = (sel < 0) ? xext : (sel == 0 ? g_xa : g_xb);
    int node = blockIdx.x;
    int t = threadIdx.x;  // 64 threads, one float4 column each
    int beg = g_rowptr[node], end = g_rowptr[node + 1];
    float4 acc = make_float4(0.f, 0.f, 0.f, 0.f);
    for (int e = beg; e < end; e++) {
        int s = g_csr[e];
        float4 v = ((const float4*)(x + (size_t)s * D))[t];
        acc.x += v.x; acc.y += v.y; acc.z += v.z; acc.w += v.w;
    }
    float inv = 1.0f / fmaxf((float)(end - beg), 1.0f);
    acc.x *= inv; acc.y *= inv; acc.z *= inv; acc.w *= inv;
    ((float4*)(g_agg + (size_t)node * D))[t] = acc;
}

// ---------------- GEMM: h = agg @ Wl + x @ Wr + bl ----------------
// viewed as [M, 512] @ [512, 256], BM=128, BN=128, BK=16, 256 threads, 8x8/thread
__global__ void __launch_bounds__(256, 2)
k_gemm(const float* __restrict__ xext, int sel,
       const float* __restrict__ Wl, const float* __restrict__ Wr,
       const float* __restrict__ bl) {
    const float* __restrict__ xcur = (sel < 0) ? xext : (sel == 0 ? g_xa : g_xb);
    __shared__ float As[16][129];
    __shared__ float Bs[16][132];
    int m0 = blockIdx.x * 128;
    int n0 = blockIdx.y * 128;
    int tid = threadIdx.x;
    int tx = tid & 15, ty = tid >> 4;
    float acc[8][8] = {};

    for (int kt = 0; kt < 2 * D; kt += 16) {
        const float* __restrict__ Asrc = (kt < D) ? g_agg : xcur;
        const float* __restrict__ Bsrc = (kt < D) ? Wl : Wr;
        int kc = kt & (D - 1);
        // load A tile 128x16 (transposed into smem)
        #pragma unroll
        for (int j = 0; j < 2; j++) {
            int idx = tid + 256 * j;
            int row = idx >> 2;
            int c4 = idx & 3;
            int grow = m0 + row;
            float4 v = make_float4(0.f, 0.f, 0.f, 0.f);
            if (grow < N_NODES)
                v = *(const float4*)(Asrc + (size_t)grow * D + kc + c4 * 4);
            As[c4 * 4 + 0][row] = v.x;
            As[c4 * 4 + 1][row] = v.y;
            As[c4 * 4 + 2][row] = v.z;
            As[c4 * 4 + 3][row] = v.w;
        }
        // load B tile 16x128
        #pragma unroll
        for (int j = 0; j < 2; j++) {
            int idx = tid + 256 * j;
            int row = idx >> 5;
            int c4 = idx & 31;
            float4 v = *(const float4*)(Bsrc + (size_t)(kc + row) * D + n0 + c4 * 4);
            *(float4*)&Bs[row][c4 * 4] = v;
        }
        __syncthreads();
        #pragma unroll
        for (int k = 0; k < 16; k++) {
            float a[8], b[8];
            #pragma unroll
            for (int i = 0; i < 8; i++) a[i] = As[k][ty * 8 + i];
            #pragma unroll
            for (int i = 0; i < 8; i++) b[i] = Bs[k][tx * 8 + i];
            #pragma unroll
            for (int i = 0; i < 8; i++)
                #pragma unroll
                for (int jj = 0; jj < 8; jj++)
                    acc[i][jj] += a[i] * b[jj];
        }
        __syncthreads();
    }
    #pragma unroll
    for (int i = 0; i < 8; i++) {
        int grow = m0 + ty * 8 + i;
        if (grow < N_NODES) {
            #pragma unroll
            for (int jj = 0; jj < 8; jj++) {
                int gcol = n0 + tx * 8 + jj;
                g_h[(size_t)grow * D + gcol] = acc[i][jj] + bl[gcol];
            }
        }
    }
}

// ---------------- BN stats ----------------
__global__ void k_zero_sums() {
    int i = threadIdx.x;
    if (i < 2 * D) g_sums[i] = 0.f;
}

__global__ void k_stats() {
    int c = threadIdx.x;  // 256
    float s = 0.f, s2 = 0.f;
    for (int r = blockIdx.x; r < N_NODES; r += gridDim.x) {
        float v = g_h[(size_t)r * D + c];
        s += v;
        s2 += v * v;
    }
    atomicAdd(&g_sums[c], s);
    atomicAdd(&g_sums[D + c], s2);
}

__global__ void k_finalize(const float* __restrict__ gamma,
                           const float* __restrict__ beta) {
    int c = threadIdx.x;
    float mu = g_sums[c] / (float)N_NODES;
    float var = g_sums[D + c] / (float)N_NODES - mu * mu;
    float rs = rsqrtf(var + BN_EPS);
    float sc = gamma[c] * rs;
    g_ss[c] = sc;
    g_ss[D + c] = beta[c] - mu * sc;
}

// ---------------- normalize + ReLU ----------------
// sel: -1 -> external out, 0 -> g_xa, 1 -> g_xb
__global__ void k_norm(float* __restrict__ oext, int sel) {
    float* __restrict__ out = (sel < 0) ? oext : (sel == 0 ? g_xa : g_xb);
    __shared__ float ss[2 * D];
    for (int i = threadIdx.x; i < 2 * D; i += blockDim.x) ss[i] = g_ss[i];
    __syncthreads();
    const int total = N_NODES * D / 4;
    for (int i = blockIdx.x * blockDim.x + threadIdx.x; i < total;
         i += gridDim.x * blockDim.x) {
        int c = (i & (D / 4 - 1)) * 4;
        float4 h = ((const float4*)g_h)[i];
        float4 r;
        r.x = fmaxf(fmaf(h.x, ss[c + 0], ss[D + c + 0]), 0.f);
        r.y = fmaxf(fmaf(h.y, ss[c + 1], ss[D + c + 1]), 0.f);
        r.z = fmaxf(fmaf(h.z, ss[c + 2], ss[D + c + 2]), 0.f);
        r.w = fmaxf(fmaf(h.w, ss[c + 3], ss[D + c + 3]), 0.f);
        ((float4*)out)[i] = r;
    }
}

// ---------------- launch ----------------
extern "C" void kernel_launch(void* const* d_in, const int* in_sizes, int n_in,
                              void* d_out, int out_size) {
    const float* x     = (const float*)d_in[0];
    const float* Wl    = (const float*)d_in[1];
    const float* bl    = (const float*)d_in[2];
    const float* Wr    = (const float*)d_in[3];
    const float* gamma = (const float*)d_in[4];
    const float* beta  = (const float*)d_in[5];
    // JAX default config disables x64: edge_index arrives as int32.
    const int* ei = (const int*)d_in[6];
    float* out = (float*)d_out;

    const int* srcp = ei;
    const int* dstp = ei + N_EDGES;

    k_zero_deg<<<(N_NODES + 255) / 256, 256>>>();
    k_count<<<(N_EDGES + 255) / 256, 256>>>(dstp);
    k_scan<<<1, 1024>>>();
    k_scatter<<<(N_EDGES + 255) / 256, 256>>>(srcp, dstp);

    int cur_sel = -1;  // layer input selector: -1 external x, 0 g_xa, 1 g_xb
    const float* cur_ext = x;
    for (int l = 0; l < NL; l++) {
        k_agg<<<N_NODES, 64>>>(cur_ext, cur_sel);
        k_zero_sums<<<1, 512>>>();
        dim3 ggrid((N_NODES + 127) / 128, 2);
        k_gemm<<<ggrid, 256>>>(cur_ext, cur_sel,
                               Wl + (size_t)l * D * D,
                               Wr + (size_t)l * D * D,
                               bl + (size_t)l * D);
        k_stats<<<512, 256>>>();
        k_finalize<<<1, 256>>>(gamma + (size_t)l * D, beta + (size_t)l * D);
        int out_sel = (l == NL - 1) ? -1 : (l & 1) == 0 ? 0 : 1;
        k_norm<<<12500, 256>>>(out, out_sel);
        cur_sel = out_sel;
        cur_ext = out;
    }
}

// round 4
// speedup vs baseline: 1.4557x; 1.4557x over previous
#include <cuda_runtime.h>
#include <mma.h>
#include <cstdint>

using namespace nvcuda;

#define N_NODES 50000
#define M_PAD 50048
#define N_EDGES 800000
#define D 256
#define K2 512
#define NL 3
#define BN_EPS 1e-5f

// ---------------- device scratch ----------------
__device__ int   g_deg[N_NODES];
__device__ int   g_rowptr[N_NODES + 1];
__device__ int   g_cursor[N_NODES];
__device__ int   g_csr[N_EDGES];
__device__ float g_agg[(size_t)M_PAD * D];
__device__ float g_h[(size_t)M_PAD * D];
__device__ float g_xa[(size_t)M_PAD * D];
__device__ float g_xb[(size_t)M_PAD * D];
__device__ float g_sums[2 * D];
__device__ float g_ss[2 * D];
__device__ float g_WT[(size_t)NL * D * K2];  // [layer][n][k]  B^T, K-major

// ---------------- helpers ----------------
__device__ __forceinline__ uint32_t smem_u32(const void* p) {
    uint32_t a;
    asm("{ .reg .u64 t; cvta.to.shared.u64 t, %1; cvt.u32.u64 %0, t; }"
        : "=r"(a) : "l"(p));
    return a;
}

__device__ __forceinline__ void cp16(uint32_t dst, const void* src, bool valid) {
    int sz = valid ? 16 : 0;
    asm volatile("cp.async.cg.shared.global [%0], [%1], 16, %2;"
                 :: "r"(dst), "l"(src), "r"(sz) : "memory");
}

// ---------------- CSR build ----------------
__global__ void k_zero_deg() {
    int i = blockIdx.x * blockDim.x + threadIdx.x;
    if (i < N_NODES) g_deg[i] = 0;
}

__global__ void k_count(const int* __restrict__ dst) {
    int e = blockIdx.x * blockDim.x + threadIdx.x;
    if (e < N_EDGES) {
        int d = dst[e];
        if (d >= 0 && d < N_NODES) atomicAdd(&g_deg[d], 1);
    }
}

__global__ void k_scan() {
    __shared__ int s[1024];
    __shared__ int carry_s;
    int tid = threadIdx.x;
    if (tid == 0) carry_s = 0;
    __syncthreads();
    for (int base = 0; base < N_NODES; base += 1024) {
        int i = base + tid;
        int v = (i < N_NODES) ? g_deg[i] : 0;
        s[tid] = v;
        __syncthreads();
        #pragma unroll
        for (int off = 1; off < 1024; off <<= 1) {
            int t = (tid >= off) ? s[tid - off] : 0;
            __syncthreads();
            s[tid] += t;
            __syncthreads();
        }
        int carry = carry_s;
        if (i < N_NODES) {
            int excl = carry + s[tid] - v;
            g_rowptr[i] = excl;
            g_cursor[i] = excl;
        }
        __syncthreads();
        if (tid == 1023) carry_s = carry + s[1023];
        __syncthreads();
    }
    if (tid == 0) g_rowptr[N_NODES] = carry_s;
}

__global__ void k_scatter(const int* __restrict__ src,
                          const int* __restrict__ dst) {
    int e = blockIdx.x * blockDim.x + threadIdx.x;
    if (e < N_EDGES) {
        int d = dst[e];
        int sv = src[e];
        if (d >= 0 && d < N_NODES && sv >= 0 && sv < N_NODES) {
            int pos = atomicAdd(&g_cursor[d], 1);
            g_csr[pos] = sv;
        }
    }
}

// ---------------- W transpose: g_WT[l][n][k] = Wcat[k][n] ----------------
__global__ void k_wt(const float* __restrict__ Wl, const float* __restrict__ Wr) {
    int l = blockIdx.y, n = blockIdx.x;
    for (int k = threadIdx.x; k < K2; k += blockDim.x) {
        float v = (k < D) ? Wl[(size_t)l * D * D + (size_t)k * D + n]
                          : Wr[(size_t)l * D * D + (size_t)(k - D) * D + n];
        g_WT[(size_t)l * D * K2 + (size_t)n * K2 + k] = v;
    }
}

// ---------------- mean aggregation ----------------
__global__ void k_agg(const float* __restrict__ xext, int sel) {
    const float* __restrict__ x = (sel < 0) ? xext : (sel == 0 ? g_xa : g_xb);
    int node = blockIdx.x;
    int t = threadIdx.x;  // 64
    int beg = g_rowptr[node], end = g_rowptr[node + 1];
    float4 acc = make_float4(0.f, 0.f, 0.f, 0.f);
    for (int e = beg; e < end; e++) {
        int s = g_csr[e];
        float4 v = ((const float4*)(x + (size_t)s * D))[t];
        acc.x += v.x; acc.y += v.y; acc.z += v.z; acc.w += v.w;
    }
    float inv = 1.0f / fmaxf((float)(end - beg), 1.0f);
    acc.x *= inv; acc.y *= inv; acc.z *= inv; acc.w *= inv;
    ((float4*)(g_agg + (size_t)node * D))[t] = acc;
}

// ---------------- wmma TF32 GEMM: g_h = concat(agg, x) @ WT^T ----------------
// block tile 128x128, BK=32, double-buffered cp.async. Bias folded into BN.
#define LDT 36                      // padded row stride (floats)
#define TILE_F (128 * LDT)          // one operand tile in floats
#define STAGE_F (2 * TILE_F)        // A + B per stage
#define GEMM_SMEM (2 * STAGE_F * 4) // bytes: 2 stages

__global__ void __launch_bounds__(256, 2)
k_gemm_tc(const float* __restrict__ xext, int sel, int layer) {
    extern __shared__ float smem[];
    const float* __restrict__ xcur = (sel < 0) ? xext : (sel == 0 ? g_xa : g_xb);
    const float* __restrict__ WT = g_WT + (size_t)layer * D * K2;
    const int tid = threadIdx.x;
    const int wid = tid >> 5;
    const int warp_m = wid & 3;       // 4 warps over M
    const int warp_n = wid >> 2;      // 2 warps over N
    const int m0 = blockIdx.x * 128;
    const int n0 = blockIdx.y * 128;
    const uint32_t smem_b = smem_u32(smem);

    wmma::fragment<wmma::accumulator, 16, 16, 8, float> c[2][4];
    #pragma unroll
    for (int i = 0; i < 2; i++)
        #pragma unroll
        for (int j = 0; j < 4; j++)
            wmma::fill_fragment(c[i][j], 0.0f);

    auto load_chunk = [&](int kc) {
        const int s = kc & 1;
        float* As = smem + s * STAGE_F;
        float* Bs = As + TILE_F;
        const float* __restrict__ Asrc = (kc < 8) ? g_agg : xcur;
        const int ka = (kc & 7) * 32;
        const int kb = kc * 32;
        #pragma unroll
        for (int i = 0; i < 4; i++) {
            int idx = tid + 256 * i;
            int row = idx >> 3, q = idx & 7;
            int gr = m0 + row;
            bool v = gr < N_NODES;
            cp16(smem_b + (uint32_t)((As - smem) + row * LDT + q * 4) * 4,
                 Asrc + (size_t)(v ? gr : 0) * D + ka + q * 4, v);
            cp16(smem_b + (uint32_t)((Bs - smem) + row * LDT + q * 4) * 4,
                 WT + (size_t)(n0 + row) * K2 + kb + q * 4, true);
        }
        asm volatile("cp.async.commit_group;" ::: "memory");
    };

    load_chunk(0);
    for (int kc = 0; kc < 16; kc++) {
        if (kc < 15) {
            load_chunk(kc + 1);
            asm volatile("cp.async.wait_group 1;" ::: "memory");
        } else {
            asm volatile("cp.async.wait_group 0;" ::: "memory");
        }
        __syncthreads();
        const int s = kc & 1;
        const float* As = smem + s * STAGE_F;
        const float* Bs = As + TILE_F;
        #pragma unroll
        for (int kk = 0; kk < 4; kk++) {
            wmma::fragment<wmma::matrix_a, 16, 16, 8, wmma::precision::tf32,
                           wmma::row_major> a[2];
            wmma::fragment<wmma::matrix_b, 16, 16, 8, wmma::precision::tf32,
                           wmma::col_major> b[4];
            #pragma unroll
            for (int i = 0; i < 2; i++) {
                wmma::load_matrix_sync(
                    a[i], As + (warp_m * 32 + i * 16) * LDT + kk * 8, LDT);
                #pragma unroll
                for (int e = 0; e < a[i].num_elements; e++)
                    a[i].x[e] = wmma::__float_to_tf32(a[i].x[e]);
            }
            #pragma unroll
            for (int j = 0; j < 4; j++) {
                wmma::load_matrix_sync(
                    b[j], Bs + (warp_n * 64 + j * 16) * LDT + kk * 8, LDT);
                #pragma unroll
                for (int e = 0; e < b[j].num_elements; e++)
                    b[j].x[e] = wmma::__float_to_tf32(b[j].x[e]);
            }
            #pragma unroll
            for (int i = 0; i < 2; i++)
                #pragma unroll
                for (int j = 0; j < 4; j++)
                    wmma::mma_sync(c[i][j], a[i], b[j], c[i][j]);
        }
        __syncthreads();
    }

    #pragma unroll
    for (int i = 0; i < 2; i++) {
        int row0 = m0 + warp_m * 32 + i * 16;
        #pragma unroll
        for (int j = 0; j < 4; j++) {
            int col0 = n0 + warp_n * 64 + j * 16;
            wmma::store_matrix_sync(g_h + (size_t)row0 * D + col0, c[i][j], D,
                                    wmma::mem_row_major);
        }
    }
}

// ---------------- BN stats / finalize / normalize ----------------
__global__ void k_zero_sums() {
    int i = threadIdx.x;
    if (i < 2 * D) g_sums[i] = 0.f;
}

__global__ void k_stats() {
    int c = threadIdx.x;  // 256
    float s = 0.f, s2 = 0.f;
    for (int r = blockIdx.x; r < N_NODES; r += gridDim.x) {
        float v = g_h[(size_t)r * D + c];
        s += v;
        s2 += v * v;
    }
    atomicAdd(&g_sums[c], s);
    atomicAdd(&g_sums[D + c], s2);
}

__global__ void k_finalize(const float* __restrict__ gamma,
                           const float* __restrict__ beta) {
    int c = threadIdx.x;
    float mu = g_sums[c] / (float)N_NODES;
    float var = g_sums[D + c] / (float)N_NODES - mu * mu;
    float rs = rsqrtf(var + BN_EPS);
    float sc = gamma[c] * rs;
    g_ss[c] = sc;
    g_ss[D + c] = beta[c] - mu * sc;   // bias bl cancels in BN exactly
}

__global__ void k_norm(float* __restrict__ oext, int sel) {
    float* __restrict__ out = (sel < 0) ? oext : (sel == 0 ? g_xa : g_xb);
    __shared__ float ss[2 * D];
    for (int i = threadIdx.x; i < 2 * D; i += blockDim.x) ss[i] = g_ss[i];
    __syncthreads();
    const int total = N_NODES * D / 4;
    for (int i = blockIdx.x * blockDim.x + threadIdx.x; i < total;
         i += gridDim.x * blockDim.x) {
        int c = (i & (D / 4 - 1)) * 4;
        float4 h = ((const float4*)g_h)[i];
        float4 r;
        r.x = fmaxf(fmaf(h.x, ss[c + 0], ss[D + c + 0]), 0.f);
        r.y = fmaxf(fmaf(h.y, ss[c + 1], ss[D + c + 1]), 0.f);
        r.z = fmaxf(fmaf(h.z, ss[c + 2], ss[D + c + 2]), 0.f);
        r.w = fmaxf(fmaf(h.w, ss[c + 3], ss[D + c + 3]), 0.f);
        ((float4*)out)[i] = r;
    }
}

// ---------------- launch ----------------
extern "C" void kernel_launch(void* const* d_in, const int* in_sizes, int n_in,
                              void* d_out, int out_size) {
    const float* x     = (const float*)d_in[0];
    const float* Wl    = (const float*)d_in[1];
    // d_in[2] = bl: mathematically cancelled by BatchNorm, unused.
    const float* Wr    = (const float*)d_in[3];
    const float* gamma = (const float*)d_in[4];
    const float* beta  = (const float*)d_in[5];
    const int*   ei    = (const int*)d_in[6];   // int32 (JAX x64 disabled)
    float* out = (float*)d_out;

    cudaFuncSetAttribute(k_gemm_tc, cudaFuncAttributeMaxDynamicSharedMemorySize,
                         GEMM_SMEM);

    const int* srcp = ei;
    const int* dstp = ei + N_EDGES;

    k_zero_deg<<<(N_NODES + 255) / 256, 256>>>();
    k_count<<<(N_EDGES + 255) / 256, 256>>>(dstp);
    k_scan<<<1, 1024>>>();
    k_scatter<<<(N_EDGES + 255) / 256, 256>>>(srcp, dstp);
    k_wt<<<dim3(256, 3), 256>>>(Wl, Wr);

    int cur_sel = -1;
    const float* cur_ext = x;
    const int n_mtiles = (N_NODES + 127) / 128;  // 391
    for (int l = 0; l < NL; l++) {
        k_agg<<<N_NODES, 64>>>(cur_ext, cur_sel);
        k_zero_sums<<<1, 512>>>();
        dim3 gg(n_mtiles, 2);
        k_gemm_tc<<<gg, 256, GEMM_SMEM>>>(cur_ext, cur_sel, l);
        k_stats<<<512, 256>>>();
        k_finalize<<<1, 256>>>(gamma + (size_t)l * D, beta + (size_t)l * D);
        int out_sel = (l == NL - 1) ? -1 : (l & 1) == 0 ? 0 : 1;
        k_norm<<<12500, 256>>>(out, out_sel);
        cur_sel = out_sel;
        cur_ext = out;
    }
}

// round 5
// speedup vs baseline: 1.4784x; 1.0156x over previous
#include <cuda_runtime.h>
#include <mma.h>
#include <cstdint>

using namespace nvcuda;

#define N_NODES 50000
#define M_PAD 50048
#define N_EDGES 800000
#define D 256
#define K2 512
#define NL 3
#define BN_EPS 1e-5f

// ---------------- device scratch ----------------
__device__ int   g_deg[N_NODES];
__device__ int   g_rowptr[N_NODES + 1];
__device__ int   g_cursor[N_NODES];
__device__ int   g_csr[N_EDGES];
__device__ float g_agg[(size_t)M_PAD * D];   // padding rows stay zero forever
__device__ float g_h[(size_t)M_PAD * D];
__device__ float g_xa[(size_t)M_PAD * D];
__device__ float g_xb[(size_t)M_PAD * D];
__device__ float g_sums[2 * D];
__device__ float g_ss[2 * D];
__device__ float g_WT[(size_t)NL * D * K2];  // [layer][n][k]  B^T, K-major

// ---------------- helpers ----------------
__device__ __forceinline__ uint32_t smem_u32(const void* p) {
    uint32_t a;
    asm("{ .reg .u64 t; cvta.to.shared.u64 t, %1; cvt.u32.u64 %0, t; }"
        : "=r"(a) : "l"(p));
    return a;
}

__device__ __forceinline__ void cp16(uint32_t dst, const void* src, bool valid) {
    int sz = valid ? 16 : 0;
    asm volatile("cp.async.cg.shared.global [%0], [%1], 16, %2;"
                 :: "r"(dst), "l"(src), "r"(sz) : "memory");
}

// ---------------- CSR build ----------------
__global__ void k_zero_deg() {
    int i = blockIdx.x * blockDim.x + threadIdx.x;
    if (i < N_NODES) g_deg[i] = 0;
}

__global__ void k_count(const int* __restrict__ dst) {
    int e = blockIdx.x * blockDim.x + threadIdx.x;
    if (e < N_EDGES) {
        int d = dst[e];
        if (d >= 0 && d < N_NODES) atomicAdd(&g_deg[d], 1);
    }
}

__global__ void k_scan() {
    __shared__ int s[1024];
    __shared__ int carry_s;
    int tid = threadIdx.x;
    if (tid == 0) carry_s = 0;
    __syncthreads();
    for (int base = 0; base < N_NODES; base += 1024) {
        int i = base + tid;
        int v = (i < N_NODES) ? g_deg[i] : 0;
        s[tid] = v;
        __syncthreads();
        #pragma unroll
        for (int off = 1; off < 1024; off <<= 1) {
            int t = (tid >= off) ? s[tid - off] : 0;
            __syncthreads();
            s[tid] += t;
            __syncthreads();
        }
        int carry = carry_s;
        if (i < N_NODES) {
            int excl = carry + s[tid] - v;
            g_rowptr[i] = excl;
            g_cursor[i] = excl;
        }
        __syncthreads();
        if (tid == 1023) carry_s = carry + s[1023];
        __syncthreads();
    }
    if (tid == 0) g_rowptr[N_NODES] = carry_s;
}

__global__ void k_scatter(const int* __restrict__ src,
                          const int* __restrict__ dst) {
    int e = blockIdx.x * blockDim.x + threadIdx.x;
    if (e < N_EDGES) {
        int d = dst[e];
        int sv = src[e];
        if (d >= 0 && d < N_NODES && sv >= 0 && sv < N_NODES) {
            int pos = atomicAdd(&g_cursor[d], 1);
            g_csr[pos] = sv;
        }
    }
}

// ---------------- W transpose: g_WT[l][n][k] = Wcat[k][n] ----------------
__global__ void k_wt(const float* __restrict__ Wl, const float* __restrict__ Wr) {
    int l = blockIdx.y, n = blockIdx.x;
    for (int k = threadIdx.x; k < K2; k += blockDim.x) {
        float v = (k < D) ? Wl[(size_t)l * D * D + (size_t)k * D + n]
                          : Wr[(size_t)l * D * D + (size_t)(k - D) * D + n];
        g_WT[(size_t)l * D * K2 + (size_t)n * K2 + k] = v;
    }
}

// ---------------- fused layer kernel ----------------
// CTA = 64 output rows x 256 cols. Phases:
//   1) mean-aggregate own 64 nodes -> g_agg  (L2 gather)
//   2) tf32 wmma GEMM  h = [agg | x] @ WT^T  (tensor pipe)
//   3) store g_h + fused BN column sums (atomics)
#define BM 64
#define LDT 36                       // padded row stride (floats)
#define A_TILE_F (BM * LDT)          // 2304 floats
#define B_TILE_F (256 * LDT)         // 9216 floats
#define STAGE_F (A_TILE_F + B_TILE_F)
#define GEMM_SMEM (2 * STAGE_F * 4)  // ~90 KB

__global__ void __launch_bounds__(256, 2)
k_layer(const float* __restrict__ xext, int sel, int layer) {
    extern __shared__ float smem[];
    const float* __restrict__ xcur = (sel < 0) ? xext : (sel == 0 ? g_xa : g_xb);
    const float* __restrict__ WT = g_WT + (size_t)layer * D * K2;
    const int tid = threadIdx.x;
    const int wid = tid >> 5, lid = tid & 31;
    const int m0 = blockIdx.x * BM;
    const uint32_t smem_b = smem_u32(smem);

    // ---- phase 1: aggregate own BM nodes (8 warps x 8 nodes each) ----
    #pragma unroll 1
    for (int i = 0; i < BM / 8; i++) {
        int node = m0 + wid * (BM / 8) + i;
        if (node < N_NODES) {
            int beg = g_rowptr[node], end = g_rowptr[node + 1];
            float4 a0 = make_float4(0.f, 0.f, 0.f, 0.f);
            float4 a1 = make_float4(0.f, 0.f, 0.f, 0.f);
            for (int e = beg; e < end; e++) {
                int s = g_csr[e];
                const float4* row = (const float4*)(xcur + (size_t)s * D);
                float4 v0 = row[lid * 2];
                float4 v1 = row[lid * 2 + 1];
                a0.x += v0.x; a0.y += v0.y; a0.z += v0.z; a0.w += v0.w;
                a1.x += v1.x; a1.y += v1.y; a1.z += v1.z; a1.w += v1.w;
            }
            float inv = 1.0f / fmaxf((float)(end - beg), 1.0f);
            a0.x *= inv; a0.y *= inv; a0.z *= inv; a0.w *= inv;
            a1.x *= inv; a1.y *= inv; a1.z *= inv; a1.w *= inv;
            float4* dst = (float4*)(g_agg + (size_t)node * D);
            __stcg(&dst[lid * 2], a0);
            __stcg(&dst[lid * 2 + 1], a1);
        }
    }
    __threadfence();   // make agg stores L2-visible to cp.async reads below
    __syncthreads();

    // ---- phase 2: GEMM ----
    const int warp_m = wid & 1;       // 2 warps over M (32 rows each)
    const int warp_n = wid >> 1;      // 4 warps over N (64 cols each)

    wmma::fragment<wmma::accumulator, 16, 16, 8, float> c[2][4];
    #pragma unroll
    for (int i = 0; i < 2; i++)
        #pragma unroll
        for (int j = 0; j < 4; j++)
            wmma::fill_fragment(c[i][j], 0.0f);

    auto load_chunk = [&](int kc) {
        const int s = kc & 1;
        float* As = smem + s * STAGE_F;
        float* Bs = As + A_TILE_F;
        const float* __restrict__ Asrc = (kc < 8) ? g_agg : xcur;
        const int ka = (kc & 7) * 32;
        const int kb = kc * 32;
        // A: 64 rows x 32 floats = 512 quads; 256 threads -> 2 each
        #pragma unroll
        for (int i = 0; i < 2; i++) {
            int idx = tid + 256 * i;
            int row = idx >> 3, q = idx & 7;
            int gr = m0 + row;
            bool v = gr < N_NODES;
            cp16(smem_b + (uint32_t)((As - smem) + row * LDT + q * 4) * 4,
                 Asrc + (size_t)(v ? gr : 0) * D + ka + q * 4, v);
        }
        // B: 256 rows x 32 floats = 2048 quads; 8 each
        #pragma unroll
        for (int i = 0; i < 8; i++) {
            int idx = tid + 256 * i;
            int row = idx >> 3, q = idx & 7;
            cp16(smem_b + (uint32_t)((Bs - smem) + row * LDT + q * 4) * 4,
                 WT + (size_t)row * K2 + kb + q * 4, true);
        }
        asm volatile("cp.async.commit_group;" ::: "memory");
    };

    load_chunk(0);
    for (int kc = 0; kc < 16; kc++) {
        if (kc < 15) {
            load_chunk(kc + 1);
            asm volatile("cp.async.wait_group 1;" ::: "memory");
        } else {
            asm volatile("cp.async.wait_group 0;" ::: "memory");
        }
        __syncthreads();
        const int s = kc & 1;
        const float* As = smem + s * STAGE_F;
        const float* Bs = As + A_TILE_F;
        #pragma unroll
        for (int kk = 0; kk < 4; kk++) {
            wmma::fragment<wmma::matrix_a, 16, 16, 8, wmma::precision::tf32,
                           wmma::row_major> a[2];
            wmma::fragment<wmma::matrix_b, 16, 16, 8, wmma::precision::tf32,
                           wmma::col_major> b[4];
            #pragma unroll
            for (int i = 0; i < 2; i++) {
                wmma::load_matrix_sync(
                    a[i], As + (warp_m * 32 + i * 16) * LDT + kk * 8, LDT);
                #pragma unroll
                for (int e = 0; e < a[i].num_elements; e++)
                    a[i].x[e] = wmma::__float_to_tf32(a[i].x[e]);
            }
            #pragma unroll
            for (int j = 0; j < 4; j++) {
                wmma::load_matrix_sync(
                    b[j], Bs + (warp_n * 64 + j * 16) * LDT + kk * 8, LDT);
                #pragma unroll
                for (int e = 0; e < b[j].num_elements; e++)
                    b[j].x[e] = wmma::__float_to_tf32(b[j].x[e]);
            }
            #pragma unroll
            for (int i = 0; i < 2; i++)
                #pragma unroll
                for (int j = 0; j < 4; j++)
                    wmma::mma_sync(c[i][j], a[i], b[j], c[i][j]);
        }
        __syncthreads();
    }

    // ---- phase 3: store h + fused BN column sums ----
    #pragma unroll
    for (int i = 0; i < 2; i++) {
        int row0 = m0 + warp_m * 32 + i * 16;
        #pragma unroll
        for (int j = 0; j < 4; j++) {
            int col0 = warp_n * 64 + j * 16;
            wmma::store_matrix_sync(g_h + (size_t)row0 * D + col0, c[i][j], D,
                                    wmma::mem_row_major);
        }
    }
    __syncthreads();
    {
        int col = tid;                      // 256 threads = 256 cols
        float s = 0.f, s2 = 0.f;
        int rmax = min(BM, N_NODES - m0);
        for (int r = 0; r < rmax; r++) {
            float v = g_h[(size_t)(m0 + r) * D + col];
            s += v;
            s2 += v * v;
        }
        atomicAdd(&g_sums[col], s);
        atomicAdd(&g_sums[D + col], s2);
    }
}

// ---------------- BN finalize / normalize ----------------
__global__ void k_zero_sums() {
    int i = threadIdx.x;
    if (i < 2 * D) g_sums[i] = 0.f;
}

__global__ void k_finalize(const float* __restrict__ gamma,
                           const float* __restrict__ beta) {
    int c = threadIdx.x;
    float mu = g_sums[c] / (float)N_NODES;
    float var = g_sums[D + c] / (float)N_NODES - mu * mu;
    float rs = rsqrtf(var + BN_EPS);
    float sc = gamma[c] * rs;
    g_ss[c] = sc;
    g_ss[D + c] = beta[c] - mu * sc;   // bias bl cancels in BN exactly
}

__global__ void k_norm(float* __restrict__ oext, int sel) {
    float* __restrict__ out = (sel < 0) ? oext : (sel == 0 ? g_xa : g_xb);
    __shared__ float ss[2 * D];
    for (int i = threadIdx.x; i < 2 * D; i += blockDim.x) ss[i] = g_ss[i];
    __syncthreads();
    const int total = N_NODES * D / 4;
    for (int i = blockIdx.x * blockDim.x + threadIdx.x; i < total;
         i += gridDim.x * blockDim.x) {
        int c = (i & (D / 4 - 1)) * 4;
        float4 h = ((const float4*)g_h)[i];
        float4 r;
        r.x = fmaxf(fmaf(h.x, ss[c + 0], ss[D + c + 0]), 0.f);
        r.y = fmaxf(fmaf(h.y, ss[c + 1], ss[D + c + 1]), 0.f);
        r.z = fmaxf(fmaf(h.z, ss[c + 2], ss[D + c + 2]), 0.f);
        r.w = fmaxf(fmaf(h.w, ss[c + 3], ss[D + c + 3]), 0.f);
        ((float4*)out)[i] = r;
    }
}

// ---------------- launch ----------------
extern "C" void kernel_launch(void* const* d_in, const int* in_sizes, int n_in,
                              void* d_out, int out_size) {
    const float* x     = (const float*)d_in[0];
    const float* Wl    = (const float*)d_in[1];
    // d_in[2] = bl: mathematically cancelled by BatchNorm, unused.
    const float* Wr    = (const float*)d_in[3];
    const float* gamma = (const float*)d_in[4];
    const float* beta  = (const float*)d_in[5];
    const int*   ei    = (const int*)d_in[6];   // int32 (JAX x64 disabled)
    float* out = (float*)d_out;

    cudaFuncSetAttribute(k_layer, cudaFuncAttributeMaxDynamicSharedMemorySize,
                         GEMM_SMEM);

    const int* srcp = ei;
    const int* dstp = ei + N_EDGES;

    k_zero_deg<<<(N_NODES + 255) / 256, 256>>>();
    k_count<<<(N_EDGES + 255) / 256, 256>>>(dstp);
    k_scan<<<1, 1024>>>();
    k_scatter<<<(N_EDGES + 255) / 256, 256>>>(srcp, dstp);
    k_wt<<<dim3(256, 3), 256>>>(Wl, Wr);

    int cur_sel = -1;
    const float* cur_ext = x;
    const int n_mtiles = (N_NODES + BM - 1) / BM;  // 782
    for (int l = 0; l < NL; l++) {
        k_zero_sums<<<1, 512>>>();
        k_layer<<<n_mtiles, 256, GEMM_SMEM>>>(cur_ext, cur_sel, l);
        k_finalize<<<1, 256>>>(gamma + (size_t)l * D, beta + (size_t)l * D);
        int out_sel = (l == NL - 1) ? -1 : (l & 1) == 0 ? 0 : 1;
        k_norm<<<12500, 256>>>(out, out_sel);
        cur_sel = out_sel;
        cur_ext = out;
    }
}

// round 7
// speedup vs baseline: 2.7195x; 1.8395x over previous
#include <cuda_runtime.h>
#include <cuda_fp16.h>
#include <mma.h>
#include <cstdint>

using namespace nvcuda;

#define N_NODES 50000
#define M_PAD 50048
#define N_EDGES 800000
#define D 256
#define K2 512
#define NL 3
#define BN_EPS 1e-5f

// ---------------- device scratch ----------------
__device__ int    g_deg[N_NODES];
__device__ int    g_rowptr[N_NODES + 1];
__device__ int    g_cursor[N_NODES];
__device__ int    g_csr[N_EDGES];
__device__ __half g_x0h[(size_t)M_PAD * D];   // fp16 cast of input x
__device__ __half g_xah[(size_t)M_PAD * D];   // layer-0 output
__device__ __half g_xbh[(size_t)M_PAD * D];   // layer-1 output
__device__ __half g_aggh[(size_t)M_PAD * D];
__device__ __half g_WTh[(size_t)NL * D * K2]; // [layer][n][k]  B^T, K-major, fp16
__device__ float  g_h[(size_t)M_PAD * D];
__device__ float  g_sums[NL][2 * D];
__device__ float  g_ss[2 * D];

// ---------------- helpers ----------------
__device__ __forceinline__ uint32_t smem_u32(const void* p) {
    uint32_t a;
    asm("{ .reg .u64 t; cvta.to.shared.u64 t, %1; cvt.u32.u64 %0, t; }"
        : "=r"(a) : "l"(p));
    return a;
}

__device__ __forceinline__ void cp16(uint32_t dst, const void* src, bool valid) {
    int sz = valid ? 16 : 0;   // sz=0 -> 16-byte zero-fill
    asm volatile("cp.async.cg.shared.global [%0], [%1], 16, %2;"
                 :: "r"(dst), "l"(src), "r"(sz) : "memory");
}

__device__ __forceinline__ void acc8(float* ac, uint4 u) {
    __half2* hp = (__half2*)&u;
    #pragma unroll
    for (int j = 0; j < 4; j++) {
        float2 f = __half22float2(hp[j]);
        ac[2 * j] += f.x;
        ac[2 * j + 1] += f.y;
    }
}

// ---------------- prep: zero deg/sums + cast x to fp16 + transpose W ----------------
__global__ void k_prep(const float* __restrict__ x,
                       const float* __restrict__ Wl,
                       const float* __restrict__ Wr) {
    int stride = gridDim.x * blockDim.x;
    int t0 = blockIdx.x * blockDim.x + threadIdx.x;
    for (int i = t0; i < N_NODES; i += stride) g_deg[i] = 0;
    for (int i = t0; i < NL * 2 * D; i += stride) ((float*)g_sums)[i] = 0.f;
    const float4* xp = (const float4*)x;
    for (int i = t0; i < N_NODES * D / 8; i += stride) {
        float4 a = xp[2 * i], b = xp[2 * i + 1];
        __half2 h0 = __floats2half2_rn(a.x, a.y);
        __half2 h1 = __floats2half2_rn(a.z, a.w);
        __half2 h2 = __floats2half2_rn(b.x, b.y);
        __half2 h3 = __floats2half2_rn(b.z, b.w);
        uint4 o;
        o.x = *(uint32_t*)&h0; o.y = *(uint32_t*)&h1;
        o.z = *(uint32_t*)&h2; o.w = *(uint32_t*)&h3;
        ((uint4*)g_x0h)[i] = o;
    }
    for (int i = t0; i < NL * D * K2; i += stride) {
        int l = i / (D * K2);
        int r = i % (D * K2);
        int n = r / K2, k = r % K2;
        float v = (k < D) ? Wl[(size_t)l * D * D + (size_t)k * D + n]
                          : Wr[(size_t)l * D * D + (size_t)(k - D) * D + n];
        g_WTh[i] = __float2half(v);
    }
}

// ---------------- CSR build ----------------
__global__ void k_count(const int* __restrict__ dst) {
    int e = blockIdx.x * blockDim.x + threadIdx.x;
    if (e < N_EDGES) {
        int d = dst[e];
        if (d >= 0 && d < N_NODES) atomicAdd(&g_deg[d], 1);
    }
}

__global__ void k_scan() {
    __shared__ int s[1024];
    __shared__ int carry_s;
    int tid = threadIdx.x;
    if (tid == 0) carry_s = 0;
    __syncthreads();
    for (int base = 0; base < N_NODES; base += 1024) {
        int i = base + tid;
        int v = (i < N_NODES) ? g_deg[i] : 0;
        s[tid] = v;
        __syncthreads();
        #pragma unroll
        for (int off = 1; off < 1024; off <<= 1) {
            int t = (tid >= off) ? s[tid - off] : 0;
            __syncthreads();
            s[tid] += t;
            __syncthreads();
        }
        int carry = carry_s;
        if (i < N_NODES) {
            int excl = carry + s[tid] - v;
            g_rowptr[i] = excl;
            g_cursor[i] = excl;
        }
        __syncthreads();
        if (tid == 1023) carry_s = carry + s[1023];
        __syncthreads();
    }
    if (tid == 0) g_rowptr[N_NODES] = carry_s;
}

__global__ void k_scatter(const int* __restrict__ src,
                          const int* __restrict__ dst) {
    int e = blockIdx.x * blockDim.x + threadIdx.x;
    if (e < N_EDGES) {
        int d = dst[e];
        int sv = src[e];
        if (d >= 0 && d < N_NODES && sv >= 0 && sv < N_NODES) {
            int pos = atomicAdd(&g_cursor[d], 1);
            g_csr[pos] = sv;
        }
    }
}

// ---------------- fused layer: agg (fp16 gather) + fp16 wmma GEMM + BN sums ----------------
// CTA tile: 64 rows x 256 cols. Warp grid 2m x 4n, warp tile 32x64.
#define BM 64
#define LDTH 72                        // padded row stride in halfs
#define A_TILE_H (BM * LDTH)           // 4608 halfs
#define B_TILE_H (256 * LDTH)          // 18432 halfs
#define STAGE_H (A_TILE_H + B_TILE_H)  // 23040 halfs
#define GEMM_SMEM (2 * STAGE_H * 2)    // 92160 bytes

__global__ void __launch_bounds__(256, 2)
k_layer(int sel, int layer) {
    extern __shared__ __half smh[];
    const __half* __restrict__ xcur =
        (sel < 0) ? g_x0h : (sel == 0 ? g_xah : g_xbh);
    const __half* __restrict__ WTh = g_WTh + (size_t)layer * D * K2;
    const int tid = threadIdx.x;
    const int wid = tid >> 5, lid = tid & 31;
    const int m0 = blockIdx.x * BM;
    const uint32_t smem_b = smem_u32(smh);

    // ---- phase 1: mean-aggregate own BM nodes (8 per warp) ----
    #pragma unroll 1
    for (int i = 0; i < BM / 8; i++) {
        int node = m0 + wid * (BM / 8) + i;
        if (node < N_NODES) {
            int beg = g_rowptr[node], end = g_rowptr[node + 1];
            float ac[8] = {0.f, 0.f, 0.f, 0.f, 0.f, 0.f, 0.f, 0.f};
            int e = beg;
            for (; e + 1 < end; e += 2) {
                int s0 = g_csr[e], s1 = g_csr[e + 1];
                uint4 u0 = ((const uint4*)(xcur + (size_t)s0 * D))[lid];
                uint4 u1 = ((const uint4*)(xcur + (size_t)s1 * D))[lid];
                acc8(ac, u0);
                acc8(ac, u1);
            }
            if (e < end) {
                uint4 u = ((const uint4*)(xcur + (size_t)g_csr[e] * D))[lid];
                acc8(ac, u);
            }
            float inv = 1.0f / fmaxf((float)(end - beg), 1.0f);
            __half2 h0 = __floats2half2_rn(ac[0] * inv, ac[1] * inv);
            __half2 h1 = __floats2half2_rn(ac[2] * inv, ac[3] * inv);
            __half2 h2 = __floats2half2_rn(ac[4] * inv, ac[5] * inv);
            __half2 h3 = __floats2half2_rn(ac[6] * inv, ac[7] * inv);
            uint4 o;
            o.x = *(uint32_t*)&h0; o.y = *(uint32_t*)&h1;
            o.z = *(uint32_t*)&h2; o.w = *(uint32_t*)&h3;
            __stcg(((uint4*)(g_aggh + (size_t)node * D)) + lid, o);
        }
    }
    __threadfence();
    __syncthreads();

    // ---- phase 2: fp16 wmma GEMM  h = [agg | x] @ WT^T ----
    const int warp_m = wid & 1;   // 2 warps over 64 rows (32 each)
    const int warp_n = wid >> 1;  // 4 warps over 256 cols (64 each)

    wmma::fragment<wmma::accumulator, 16, 16, 16, float> c[2][4];
    #pragma unroll
    for (int i = 0; i < 2; i++)
        #pragma unroll
        for (int j = 0; j < 4; j++)
            wmma::fill_fragment(c[i][j], 0.0f);

    auto load_chunk = [&](int kc) {
        const int s = kc & 1;
        __half* As = smh + s * STAGE_H;
        __half* Bs = As + A_TILE_H;
        const __half* __restrict__ Asrc = (kc < 4) ? g_aggh : xcur;
        const int ka = (kc & 3) * 64;
        const int kb = kc * 64;
        // A: 64 rows x 64 halfs = 512 quads, 2/thread
        #pragma unroll
        for (int i = 0; i < 2; i++) {
            int idx = tid + 256 * i;
            int row = idx >> 3, q = idx & 7;
            int gr = m0 + row;
            bool v = gr < N_NODES;
            cp16(smem_b + (uint32_t)((As - smh) + row * LDTH + q * 8) * 2,
                 Asrc + (size_t)(v ? gr : 0) * D + ka + q * 8, v);
        }
        // B: 256 rows x 64 halfs = 2048 quads, 8/thread
        #pragma unroll
        for (int i = 0; i < 8; i++) {
            int idx = tid + 256 * i;
            int row = idx >> 3, q = idx & 7;
            cp16(smem_b + (uint32_t)((Bs - smh) + row * LDTH + q * 8) * 2,
                 WTh + (size_t)row * K2 + kb + q * 8, true);
        }
        asm volatile("cp.async.commit_group;" ::: "memory");
    };

    load_chunk(0);
    for (int kc = 0; kc < 8; kc++) {
        if (kc < 7) {
            load_chunk(kc + 1);
            asm volatile("cp.async.wait_group 1;" ::: "memory");
        } else {
            asm volatile("cp.async.wait_group 0;" ::: "memory");
        }
        __syncthreads();
        const int s = kc & 1;
        const __half* As = smh + s * STAGE_H;
        const __half* Bs = As + A_TILE_H;
        #pragma unroll
        for (int kk = 0; kk < 4; kk++) {
            wmma::fragment<wmma::matrix_a, 16, 16, 16, __half,
                           wmma::row_major> a[2];
            #pragma unroll
            for (int i = 0; i < 2; i++)
                wmma::load_matrix_sync(
                    a[i], As + (warp_m * 32 + i * 16) * LDTH + kk * 16, LDTH);
            #pragma unroll
            for (int j = 0; j < 4; j++) {
                wmma::fragment<wmma::matrix_b, 16, 16, 16, __half,
                               wmma::col_major> b;
                wmma::load_matrix_sync(
                    b, Bs + (warp_n * 64 + j * 16) * LDTH + kk * 16, LDTH);
                wmma::mma_sync(c[0][j], a[0], b, c[0][j]);
                wmma::mma_sync(c[1][j], a[1], b, c[1][j]);
            }
        }
        __syncthreads();
    }

    // ---- phase 3: store h + fused BN column sums ----
    #pragma unroll
    for (int i = 0; i < 2; i++) {
        int row0 = m0 + warp_m * 32 + i * 16;
        #pragma unroll
        for (int j = 0; j < 4; j++) {
            int col0 = warp_n * 64 + j * 16;
            wmma::store_matrix_sync(g_h + (size_t)row0 * D + col0, c[i][j], D,
                                    wmma::mem_row_major);
        }
    }
    __syncthreads();
    {
        int col = tid;
        float s = 0.f, s2 = 0.f;
        int rmax = min(BM, N_NODES - m0);
        for (int r = 0; r < rmax; r++) {
            float v = g_h[(size_t)(m0 + r) * D + col];
            s += v;
            s2 += v * v;
        }
        atomicAdd(&g_sums[layer][col], s);
        atomicAdd(&g_sums[layer][D + col], s2);
    }
}

// ---------------- BN finalize / normalize ----------------
__global__ void k_finalize(int layer, const float* __restrict__ gamma,
                           const float* __restrict__ beta) {
    int c = threadIdx.x;
    float mu = g_sums[layer][c] / (float)N_NODES;
    float var = g_sums[layer][D + c] / (float)N_NODES - mu * mu;
    float rs = rsqrtf(var + BN_EPS);
    float sc = gamma[c] * rs;
    g_ss[c] = sc;
    g_ss[D + c] = beta[c] - mu * sc;   // bias bl cancels in BN exactly
}

// intermediate layers: write fp16
__global__ void k_norm_h(int sel_out) {
    __half* __restrict__ out = (sel_out == 0) ? g_xah : g_xbh;
    __shared__ float ss[2 * D];
    for (int i = threadIdx.x; i < 2 * D; i += blockDim.x) ss[i] = g_ss[i];
    __syncthreads();
    const int total = N_NODES * D / 8;
    const float4* hp = (const float4*)g_h;
    for (int i = blockIdx.x * blockDim.x + threadIdx.x; i < total;
         i += gridDim.x * blockDim.x) {
        int c = (i & 31) * 8;
        float4 h0 = hp[2 * i], h1 = hp[2 * i + 1];
        float r0 = fmaxf(fmaf(h0.x, ss[c + 0], ss[D + c + 0]), 0.f);
        float r1 = fmaxf(fmaf(h0.y, ss[c + 1], ss[D + c + 1]), 0.f);
        float r2 = fmaxf(fmaf(h0.z, ss[c + 2], ss[D + c + 2]), 0.f);
        float r3 = fmaxf(fmaf(h0.w, ss[c + 3], ss[D + c + 3]), 0.f);
        float r4 = fmaxf(fmaf(h1.x, ss[c + 4], ss[D + c + 4]), 0.f);
        float r5 = fmaxf(fmaf(h1.y, ss[c + 5], ss[D + c + 5]), 0.f);
        float r6 = fmaxf(fmaf(h1.z, ss[c + 6], ss[D + c + 6]), 0.f);
        float r7 = fmaxf(fmaf(h1.w, ss[c + 7], ss[D + c + 7]), 0.f);
        __half2 q0 = __floats2half2_rn(r0, r1);
        __half2 q1 = __floats2half2_rn(r2, r3);
        __half2 q2 = __floats2half2_rn(r4, r5);
        __half2 q3 = __floats2half2_rn(r6, r7);
        uint4 o;
        o.x = *(uint32_t*)&q0; o.y = *(uint32_t*)&q1;
        o.z = *(uint32_t*)&q2; o.w = *(uint32_t*)&q3;
        ((uint4*)out)[i] = o;
    }
}

// final layer: write fp32
__global__ void k_norm_f(float* __restrict__ out) {
    __shared__ float ss[2 * D];
    for (int i = threadIdx.x; i < 2 * D; i += blockDim.x) ss[i] = g_ss[i];
    __syncthreads();
    const int total = N_NODES * D / 4;
    for (int i = blockIdx.x * blockDim.x + threadIdx.x; i < total;
         i += gridDim.x * blockDim.x) {
        int c = (i & (D / 4 - 1)) * 4;
        float4 h = ((const float4*)g_h)[i];
        float4 r;
        r.x = fmaxf(fmaf(h.x, ss[c + 0], ss[D + c + 0]), 0.f);
        r.y = fmaxf(fmaf(h.y, ss[c + 1], ss[D + c + 1]), 0.f);
        r.z = fmaxf(fmaf(h.z, ss[c + 2], ss[D + c + 2]), 0.f);
        r.w = fmaxf(fmaf(h.w, ss[c + 3], ss[D + c + 3]), 0.f);
        ((float4*)out)[i] = r;
    }
}

// ---------------- launch ----------------
extern "C" void kernel_launch(void* const* d_in, const int* in_sizes, int n_in,
                              void* d_out, int out_size) {
    const float* x     = (const float*)d_in[0];
    const float* Wl    = (const float*)d_in[1];
    // d_in[2] = bl: cancelled exactly by BatchNorm, unused.
    const float* Wr    = (const float*)d_in[3];
    const float* gamma = (const float*)d_in[4];
    const float* beta  = (const float*)d_in[5];
    const int*   ei    = (const int*)d_in[6];   // int32 (JAX x64 disabled)
    float* out = (float*)d_out;

    cudaFuncSetAttribute(k_layer, cudaFuncAttributeMaxDynamicSharedMemorySize,
                         GEMM_SMEM);

    const int* srcp = ei;
    const int* dstp = ei + N_EDGES;

    k_prep<<<4096, 256>>>(x, Wl, Wr);
    k_count<<<(N_EDGES + 255) / 256, 256>>>(dstp);
    k_scan<<<1, 1024>>>();
    k_scatter<<<(N_EDGES + 255) / 256, 256>>>(srcp, dstp);

    const int n_mtiles = (N_NODES + BM - 1) / BM;  // 782
    int cur_sel = -1;
    for (int l = 0; l < NL; l++) {
        k_layer<<<n_mtiles, 256, GEMM_SMEM>>>(cur_sel, l);
        k_finalize<<<1, 256>>>(l, gamma + (size_t)l * D, beta + (size_t)l * D);
        if (l < NL - 1) {
            int out_sel = (l == 0) ? 0 : 1;
            k_norm_h<<<6250, 256>>>(out_sel);
            cur_sel = out_sel;
        } else {
            k_norm_f<<<12500, 256>>>(out);
        }
    }
}